// round 4
// baseline (speedup 1.0000x reference)
#include <cuda_runtime.h>

// ---------------------------------------------------------------------------
// Problem constants
// ---------------------------------------------------------------------------
#define NB   8                 // batch
#define NP   8192              // points per batch
#define NM   (NB * NP)         // 65536 total rows
#define NK   128               // codes per record
#define ND   128               // code dim
#define XLD  132               // padded leading dim for x (131 valid + 1 pad)
#define PPB  128               // points per block in stage-1

// ---------------------------------------------------------------------------
// Scratch (static __device__ — no allocations allowed)
// ---------------------------------------------------------------------------
__device__ float g_x [(size_t)NM * XLD ];   //  34.6 MB
__device__ float g_h1[(size_t)NM * 2048];   // 536   MB
__device__ float g_h2[(size_t)NM * 1024];   // 268   MB
__device__ float g_h3[(size_t)NM * 512 ];   // 134   MB
__device__ float g_h4[(size_t)NM * 256 ];   //  67   MB
__device__ float g_h5[(size_t)NM * 128 ];   //  33.5 MB

// ---------------------------------------------------------------------------
// Stage 1: inverse-square-distance weighted code interpolation.
// One CTA = one (batch, chunk-of-128-points). Codes tile (128x128 f32, 64KB)
// staged in dynamic smem; code positions live in per-lane registers (4 codes
// per lane). One warp processes one point at a time.
// x[m, 0:128] = query_codes, x[m, 128:131] = query_point, x[m,131] = 0.
// ---------------------------------------------------------------------------
__global__ void stage1_kernel(const int* __restrict__ indices,
                              const float* __restrict__ qp,
                              const float* __restrict__ codes_pos,
                              const float* __restrict__ codes)
{
    extern __shared__ float smem[];
    float4* bc4 = reinterpret_cast<float4*>(smem);   // [128 codes][32 float4] = codes[k][d]
    float*  ws  = smem + NK * ND;                    // [8 warps][128] weights

    const int b   = blockIdx.x;
    const int rec = indices[b];

    // codes[rec] row-major (k,d) == linear float4 index k*32+d4 : direct copy
    const float4* csrc = reinterpret_cast<const float4*>(codes + (size_t)rec * NK * ND);
    for (int i = threadIdx.x; i < NK * (ND / 4); i += blockDim.x)
        bc4[i] = csrc[i];
    __syncthreads();

    const int warp = threadIdx.x >> 5;
    const int lane = threadIdx.x & 31;

    // per-lane code positions: k = lane + 32*t
    const float* pbase = codes_pos + (size_t)rec * NK * 3;
    float cpx[4], cpy[4], cpz[4];
#pragma unroll
    for (int t = 0; t < 4; t++) {
        int k = lane + 32 * t;
        cpx[t] = pbase[k * 3 + 0];
        cpy[t] = pbase[k * 3 + 1];
        cpz[t] = pbase[k * 3 + 2];
    }

    float* wsw = ws + warp * NK;
    const int p0 = blockIdx.y * PPB;

    for (int pi = warp; pi < PPB; pi += 8) {
        const int p = p0 + pi;
        const int m = b * NP + p;
        const float qx = qp[(size_t)m * 3 + 0];
        const float qy = qp[(size_t)m * 3 + 1];
        const float qz = qp[(size_t)m * 3 + 2];

        float wsum = 0.f;
#pragma unroll
        for (int t = 0; t < 4; t++) {
            float dx = qx - cpx[t], dy = qy - cpy[t], dz = qz - cpz[t];
            float sq = dx * dx + dy * dy + dz * dz + 1e-16f;
            float w  = 1.0f / sq;           // DIST_SCALE=2 -> sd^(-1)
            wsw[lane + 32 * t] = w;
            wsum += w;
        }
        __syncwarp();
#pragma unroll
        for (int o = 16; o > 0; o >>= 1)
            wsum += __shfl_xor_sync(0xffffffffu, wsum, o);

        float4 acc = make_float4(0.f, 0.f, 0.f, 0.f);
#pragma unroll 4
        for (int k = 0; k < NK; k++) {
            const float  w = wsw[k];
            const float4 c = bc4[k * 32 + lane];
            acc.x = fmaf(w, c.x, acc.x);
            acc.y = fmaf(w, c.y, acc.y);
            acc.z = fmaf(w, c.z, acc.z);
            acc.w = fmaf(w, c.w, acc.w);
        }
        const float inv = 1.0f / wsum;
        acc.x *= inv; acc.y *= inv; acc.z *= inv; acc.w *= inv;

        float* xrow = g_x + (size_t)m * XLD;
        reinterpret_cast<float4*>(xrow)[lane] = acc;     // d = 4*lane .. 4*lane+3
        if (lane == 0) {
            xrow[128] = qx; xrow[129] = qy; xrow[130] = qz; xrow[131] = 0.f;
        }
        __syncwarp();   // all lanes done reading wsw before next overwrite
    }
}

// ---------------------------------------------------------------------------
// Generic fused layer GEMM:
//   Out[m,n] = act( sum_{k<K1} Hin[m,k]*W[k,n] + sum_{k<K2} X[m,k]*W[K1+k,n] + bias[n] )
// (handles the skip-concat [h, x] without materializing it)
// 128x128x16 block tile, 256 threads, 8x8 register micro-tile, fp32.
// M = 65536 (multiple of 128), N multiple of 128; K tail zero-padded in smem.
// ---------------------------------------------------------------------------
__global__ __launch_bounds__(256, 2)
void gemm_kernel(const float* __restrict__ Hin, int K1,
                 const float* __restrict__ X,   int K2,
                 const float* __restrict__ W,   const float* __restrict__ bias,
                 float* __restrict__ Out, int N, int relu)
{
    __shared__ float As[16][132];   // transposed A tile, padded vs bank conflicts
    __shared__ float Bs[16][128];

    const int t  = threadIdx.x;
    const int tm = t >> 4;          // 0..15 -> output rows tm*8..tm*8+7
    const int tn = t & 15;          // 0..15 -> output cols tn*8..tn*8+7
    const int bm = blockIdx.x;
    const int bn = blockIdx.y;

    const int Ktot = K1 + K2;
    const int kt   = (Ktot + 15) >> 4;

    // A-tile loader mapping: 2048 elems / 256 thr = 8 each (one half-row)
    const int lr  = t >> 1;          // 0..127 (m within tile)
    const int lc0 = (t & 1) << 3;    // 0 or 8 (k within tile)
    // B-tile loader mapping: row rb (k), 8 consecutive cols
    const int rb  = t >> 4;          // 0..15
    const int cb0 = (t & 15) << 3;   // 0..120

    const int mA = bm * 128 + lr;

    float acc[8][8];
#pragma unroll
    for (int i = 0; i < 8; i++)
#pragma unroll
        for (int j = 0; j < 8; j++) acc[i][j] = 0.f;

    for (int it = 0; it < kt; ++it) {
        const int k0 = it << 4;

        // ---- load A tile (store transposed) ----
        {
            const int kA = k0 + lc0;
            float v[8];
            if (kA + 7 < K1) {                               // fully in Hin
                const float4* s = reinterpret_cast<const float4*>(Hin + (size_t)mA * K1 + kA);
                float4 u0 = s[0], u1 = s[1];
                v[0]=u0.x; v[1]=u0.y; v[2]=u0.z; v[3]=u0.w;
                v[4]=u1.x; v[5]=u1.y; v[6]=u1.z; v[7]=u1.w;
            } else if (kA >= K1 && kA + 7 < Ktot) {          // fully in X
                const float4* s = reinterpret_cast<const float4*>(X + (size_t)mA * XLD + (kA - K1));
                float4 u0 = s[0], u1 = s[1];
                v[0]=u0.x; v[1]=u0.y; v[2]=u0.z; v[3]=u0.w;
                v[4]=u1.x; v[5]=u1.y; v[6]=u1.z; v[7]=u1.w;
            } else {                                          // boundary: scalar guarded
#pragma unroll
                for (int i = 0; i < 8; i++) {
                    int k = kA + i;
                    float u = 0.f;
                    if (k < K1)        u = Hin[(size_t)mA * K1 + k];
                    else if (k < Ktot) u = X[(size_t)mA * XLD + (k - K1)];
                    v[i] = u;
                }
            }
#pragma unroll
            for (int i = 0; i < 8; i++) As[lc0 + i][lr] = v[i];
        }
        // ---- load B tile ----
        {
            const int kB = k0 + rb;
            float4 u0, u1;
            if (kB < Ktot) {
                const float4* s = reinterpret_cast<const float4*>(W + (size_t)kB * N + bn * 128 + cb0);
                u0 = s[0]; u1 = s[1];
            } else {
                u0 = make_float4(0.f, 0.f, 0.f, 0.f); u1 = u0;
            }
            *reinterpret_cast<float4*>(&Bs[rb][cb0])     = u0;
            *reinterpret_cast<float4*>(&Bs[rb][cb0 + 4]) = u1;
        }
        __syncthreads();

#pragma unroll
        for (int k = 0; k < 16; k++) {
            float a[8], b[8];
            float4 a0 = *reinterpret_cast<const float4*>(&As[k][tm * 8]);
            float4 a1 = *reinterpret_cast<const float4*>(&As[k][tm * 8 + 4]);
            float4 c0 = *reinterpret_cast<const float4*>(&Bs[k][tn * 8]);
            float4 c1 = *reinterpret_cast<const float4*>(&Bs[k][tn * 8 + 4]);
            a[0]=a0.x; a[1]=a0.y; a[2]=a0.z; a[3]=a0.w;
            a[4]=a1.x; a[5]=a1.y; a[6]=a1.z; a[7]=a1.w;
            b[0]=c0.x; b[1]=c0.y; b[2]=c0.z; b[3]=c0.w;
            b[4]=c1.x; b[5]=c1.y; b[6]=c1.z; b[7]=c1.w;
#pragma unroll
            for (int i = 0; i < 8; i++)
#pragma unroll
                for (int j = 0; j < 8; j++)
                    acc[i][j] = fmaf(a[i], b[j], acc[i][j]);
        }
        __syncthreads();
    }

    // ---- epilogue: bias + leaky-relu + store ----
    float bv[8];
#pragma unroll
    for (int j = 0; j < 8; j++) bv[j] = bias[bn * 128 + tn * 8 + j];

#pragma unroll
    for (int i = 0; i < 8; i++) {
        const size_t row = (size_t)(bm * 128 + tm * 8 + i);
        float o[8];
#pragma unroll
        for (int j = 0; j < 8; j++) {
            float v = acc[i][j] + bv[j];
            if (relu) v = (v > 0.f) ? v : 0.02f * v;
            o[j] = v;
        }
        float* dst = Out + row * N + bn * 128 + tn * 8;
        *reinterpret_cast<float4*>(dst)     = make_float4(o[0], o[1], o[2], o[3]);
        *reinterpret_cast<float4*>(dst + 4) = make_float4(o[4], o[5], o[6], o[7]);
    }
}

// ---------------------------------------------------------------------------
// Final layer: out[m] = h5[m,:] . W6 + b6   (128 -> 1). Warp per point.
// ---------------------------------------------------------------------------
__global__ void final_kernel(const float* __restrict__ h5,
                             const float* __restrict__ W6,
                             const float* __restrict__ b6,
                             float* __restrict__ out)
{
    const int warp = threadIdx.x >> 5;
    const int lane = threadIdx.x & 31;
    const int m = blockIdx.x * 8 + warp;

    const float4 h = reinterpret_cast<const float4*>(h5 + (size_t)m * 128)[lane];
    const float4 w = reinterpret_cast<const float4*>(W6)[lane];
    float s = h.x * w.x + h.y * w.y + h.z * w.z + h.w * w.w;
#pragma unroll
    for (int o = 16; o > 0; o >>= 1)
        s += __shfl_xor_sync(0xffffffffu, s, o);
    if (lane == 0) out[m] = s + b6[0];
}

// ---------------------------------------------------------------------------
// Launch
// ---------------------------------------------------------------------------
extern "C" void kernel_launch(void* const* d_in, const int* in_sizes, int n_in,
                              void* d_out, int out_size)
{
    (void)in_sizes; (void)n_in; (void)out_size;

    const int*   indices = (const int*)  d_in[0];
    const float* qp      = (const float*)d_in[1];
    const float* cpos    = (const float*)d_in[2];
    const float* codes   = (const float*)d_in[3];
    const float* W1 = (const float*)d_in[4];  const float* b1 = (const float*)d_in[5];
    const float* W2 = (const float*)d_in[6];  const float* b2 = (const float*)d_in[7];
    const float* W3 = (const float*)d_in[8];  const float* b3 = (const float*)d_in[9];
    const float* W4 = (const float*)d_in[10]; const float* b4 = (const float*)d_in[11];
    const float* W5 = (const float*)d_in[12]; const float* b5 = (const float*)d_in[13];
    const float* W6 = (const float*)d_in[14]; const float* b6 = (const float*)d_in[15];
    float* out = (float*)d_out;

    float *px, *ph1, *ph2, *ph3, *ph4, *ph5;
    cudaGetSymbolAddress((void**)&px,  g_x);
    cudaGetSymbolAddress((void**)&ph1, g_h1);
    cudaGetSymbolAddress((void**)&ph2, g_h2);
    cudaGetSymbolAddress((void**)&ph3, g_h3);
    cudaGetSymbolAddress((void**)&ph4, g_h4);
    cudaGetSymbolAddress((void**)&ph5, g_h5);

    const int s1_smem = NK * ND * (int)sizeof(float) + 8 * NK * (int)sizeof(float); // 69632
    cudaFuncSetAttribute(stage1_kernel, cudaFuncAttributeMaxDynamicSharedMemorySize, s1_smem);

    // Stage 1: x = [weighted codes, query_point]
    stage1_kernel<<<dim3(NB, NP / PPB), 256, s1_smem>>>(indices, qp, cpos, codes);

    // MLP: out = lrelu(h @ W[:K1] + x @ W[K1:] + b)
    gemm_kernel<<<dim3(NM / 128, 16), 256>>>(px,  0,    px, 131, W1, b1, ph1, 2048, 1);
    gemm_kernel<<<dim3(NM / 128, 8 ), 256>>>(ph1, 2048, px, 131, W2, b2, ph2, 1024, 1);
    gemm_kernel<<<dim3(NM / 128, 4 ), 256>>>(ph2, 1024, px, 131, W3, b3, ph3, 512,  1);
    gemm_kernel<<<dim3(NM / 128, 2 ), 256>>>(ph3, 512,  px, 131, W4, b4, ph4, 256,  1);
    gemm_kernel<<<dim3(NM / 128, 1 ), 256>>>(ph4, 256,  px, 131, W5, b5, ph5, 128,  1);

    // Final 128 -> 1 dot
    final_kernel<<<NM / 8, 256>>>(ph5, W6, b6, out);
}

// round 6
// speedup vs baseline: 2.8945x; 2.8945x over previous
#include <cuda_runtime.h>
#include <cuda_bf16.h>
#include <stdint.h>

// ---------------------------------------------------------------------------
// Problem constants
// ---------------------------------------------------------------------------
#define NB   8
#define NP   8192
#define NM   (NB * NP)          // 65536 rows
#define NK   128                // codes per record
#define ND   128                // code dim
#define XK   160                // padded x K-dim (131 valid, rest zero) — mult of 32
#define PPB  128                // stage-1 points per block

// ---------------------------------------------------------------------------
// Scratch: bf16 hi/lo activation planes + split weights (no allocs allowed)
// ---------------------------------------------------------------------------
__device__ __nv_bfloat16 g_xhi[(size_t)NM * XK];
__device__ __nv_bfloat16 g_xlo[(size_t)NM * XK];
__device__ __nv_bfloat16 g_h1hi[(size_t)NM * 2048];
__device__ __nv_bfloat16 g_h1lo[(size_t)NM * 2048];
__device__ __nv_bfloat16 g_h2hi[(size_t)NM * 1024];
__device__ __nv_bfloat16 g_h2lo[(size_t)NM * 1024];
__device__ __nv_bfloat16 g_h3hi[(size_t)NM * 512];
__device__ __nv_bfloat16 g_h3lo[(size_t)NM * 512];
__device__ __nv_bfloat16 g_h4hi[(size_t)NM * 256];
__device__ __nv_bfloat16 g_h4lo[(size_t)NM * 256];
__device__ __nv_bfloat16 g_h5hi[(size_t)NM * 128];
__device__ __nv_bfloat16 g_h5lo[(size_t)NM * 128];
// split weights: sum of (K1 + 160)*N*2 planes over 5 layers = 6,840,320 elems
__device__ __nv_bfloat16 g_wsplit[6840320];

// ---------------------------------------------------------------------------
// Helpers
// ---------------------------------------------------------------------------
__device__ __forceinline__ void split_store(__nv_bfloat16* hp, __nv_bfloat16* lp, float v)
{
    __nv_bfloat16 h = __float2bfloat16(v);
    *hp = h;
    *lp = __float2bfloat16(v - __bfloat162float(h));
}

__device__ __forceinline__ uint32_t smem_u32(const void* p)
{
    return (uint32_t)__cvta_generic_to_shared(p);
}

template<int Ngrp> __device__ __forceinline__ void cp_wait()
{
    asm volatile("cp.async.wait_group %0;\n" :: "n"(Ngrp));
}

#define CP16(dst_u32, src_ptr) \
    asm volatile("cp.async.cg.shared.global [%0], [%1], 16;\n" :: "r"(dst_u32), "l"(src_ptr))

__device__ __forceinline__ void ldsm_x4(uint32_t* r, uint32_t addr)
{
    asm volatile("ldmatrix.sync.aligned.m8n8.x4.shared.b16 {%0,%1,%2,%3}, [%4];\n"
                 : "=r"(r[0]), "=r"(r[1]), "=r"(r[2]), "=r"(r[3]) : "r"(addr));
}

__device__ __forceinline__ void ldsm_x4_t(uint32_t* r, uint32_t addr)
{
    asm volatile("ldmatrix.sync.aligned.m8n8.x4.trans.shared.b16 {%0,%1,%2,%3}, [%4];\n"
                 : "=r"(r[0]), "=r"(r[1]), "=r"(r[2]), "=r"(r[3]) : "r"(addr));
}

__device__ __forceinline__ void mma16816(float* d, const uint32_t* a, uint32_t b0, uint32_t b1)
{
    asm volatile(
        "mma.sync.aligned.m16n8k16.row.col.f32.bf16.bf16.f32 "
        "{%0,%1,%2,%3}, {%4,%5,%6,%7}, {%8,%9}, {%0,%1,%2,%3};\n"
        : "+f"(d[0]), "+f"(d[1]), "+f"(d[2]), "+f"(d[3])
        : "r"(a[0]), "r"(a[1]), "r"(a[2]), "r"(a[3]), "r"(b0), "r"(b1));
}

// ---------------------------------------------------------------------------
// Stage 1: inverse-square-distance weighted code interpolation -> x planes
// x[m, 0:128] = weighted codes, x[m,128:131] = query point, 131..159 = 0
// ---------------------------------------------------------------------------
__global__ void stage1_kernel(const int* __restrict__ indices,
                              const float* __restrict__ qp,
                              const float* __restrict__ codes_pos,
                              const float* __restrict__ codes)
{
    extern __shared__ float smem[];
    float4* bc4 = reinterpret_cast<float4*>(smem);   // [128 codes][32 float4]
    float*  ws  = smem + NK * ND;                    // [8 warps][128] weights

    const int b   = blockIdx.x;
    const int rec = indices[b];

    const float4* csrc = reinterpret_cast<const float4*>(codes + (size_t)rec * NK * ND);
    for (int i = threadIdx.x; i < NK * (ND / 4); i += blockDim.x)
        bc4[i] = csrc[i];
    __syncthreads();

    const int warp = threadIdx.x >> 5;
    const int lane = threadIdx.x & 31;

    const float* pbase = codes_pos + (size_t)rec * NK * 3;
    float cpx[4], cpy[4], cpz[4];
#pragma unroll
    for (int t = 0; t < 4; t++) {
        int k = lane + 32 * t;
        cpx[t] = pbase[k * 3 + 0];
        cpy[t] = pbase[k * 3 + 1];
        cpz[t] = pbase[k * 3 + 2];
    }

    float* wsw = ws + warp * NK;
    const int p0 = blockIdx.y * PPB;

    for (int pi = warp; pi < PPB; pi += 8) {
        const int m = b * NP + p0 + pi;
        const float qx = qp[(size_t)m * 3 + 0];
        const float qy = qp[(size_t)m * 3 + 1];
        const float qz = qp[(size_t)m * 3 + 2];

        float wsum = 0.f;
#pragma unroll
        for (int t = 0; t < 4; t++) {
            float dx = qx - cpx[t], dy = qy - cpy[t], dz = qz - cpz[t];
            float sq = dx * dx + dy * dy + dz * dz + 1e-16f;
            float w  = 1.0f / sq;
            wsw[lane + 32 * t] = w;
            wsum += w;
        }
        __syncwarp();
#pragma unroll
        for (int o = 16; o > 0; o >>= 1)
            wsum += __shfl_xor_sync(0xffffffffu, wsum, o);

        float4 acc = make_float4(0.f, 0.f, 0.f, 0.f);
#pragma unroll 4
        for (int k = 0; k < NK; k++) {
            const float  w = wsw[k];
            const float4 c = bc4[k * 32 + lane];
            acc.x = fmaf(w, c.x, acc.x);
            acc.y = fmaf(w, c.y, acc.y);
            acc.z = fmaf(w, c.z, acc.z);
            acc.w = fmaf(w, c.w, acc.w);
        }
        const float inv = 1.0f / wsum;

        __nv_bfloat16* xh = g_xhi + (size_t)m * XK;
        __nv_bfloat16* xl = g_xlo + (size_t)m * XK;
        float v[4] = { acc.x * inv, acc.y * inv, acc.z * inv, acc.w * inv };
#pragma unroll
        for (int j = 0; j < 4; j++)
            split_store(xh + 4 * lane + j, xl + 4 * lane + j, v[j]);

        // tail cols 128..159: query point then zeros (one col per lane)
        {
            const int c = 128 + lane;
            float q = 0.f;
            if (lane == 0) q = qx; else if (lane == 1) q = qy; else if (lane == 2) q = qz;
            split_store(xh + c, xl + c, q);
        }
        __syncwarp();
    }
}

// ---------------------------------------------------------------------------
// Weight prep: fp32 W[K1+131, N] -> bf16 hi/lo planes, x-part padded to 160 rows
// ---------------------------------------------------------------------------
__global__ void prep_w(const float* __restrict__ W, int K1, int N,
                       __nv_bfloat16* __restrict__ hh, __nv_bfloat16* __restrict__ hl,
                       __nv_bfloat16* __restrict__ xh, __nv_bfloat16* __restrict__ xl)
{
    const int idx = blockIdx.x * blockDim.x + threadIdx.x;
    const int tot = (K1 + XK) * N;
    if (idx >= tot) return;
    const int r = idx / N, n = idx - r * N;
    if (r < K1) {
        split_store(hh + (size_t)r * N + n, hl + (size_t)r * N + n, W[(size_t)r * N + n]);
    } else {
        const int r2 = r - K1;
        float v = (r2 < 131) ? W[(size_t)(K1 + r2) * N + n] : 0.f;
        split_store(xh + (size_t)r2 * N + n, xl + (size_t)r2 * N + n, v);
    }
}

// ---------------------------------------------------------------------------
// Segmented bf16 tensor-core GEMM with fused bias + leaky-relu + hi/lo store.
//   Out[m,n] = act( sum_seg  A_seg[m,:] @ B_seg[:,n]  + bias[n] )
// CTA 128x128, 8 warps (32x64 each), K-chunks of 32, cp.async double buffer.
// All segment K's are multiples of 32; M, N multiples of 128.
// ---------------------------------------------------------------------------
struct Seg { const __nv_bfloat16* A; const __nv_bfloat16* B; int lda; int kchunks; };
struct SegList { Seg s[6]; int n; };

__global__ __launch_bounds__(256, 2)
void mma_gemm(SegList SL, const float* __restrict__ bias, int N,
              __nv_bfloat16* __restrict__ out_hi, __nv_bfloat16* __restrict__ out_lo)
{
    __shared__ uint4 As4[2][512];   // [buf][m(128) x chunk(4)] xor-swizzled
    __shared__ uint4 Bs4[2][512];   // [buf][k(32) x chunk(16)] xor-swizzled

    const int t    = threadIdx.x;
    const int lane = t & 31;
    const int w    = t >> 5;
    const int wm   = (w & 3) * 32;   // warp M offset in tile
    const int wn   = (w >> 2) * 64;  // warp N offset in tile

    const int n0 = blockIdx.x * 128;
    const int m0 = blockIdx.y * 128;

    // loader thread-fixed coordinates
    const int am = t >> 2, ac = t & 3;
    const int aoff0 = am * 4        + (ac ^ ((am >> 1) & 3));
    const int aoff1 = (am + 64) * 4 + (ac ^ ((am >> 1) & 3));
    const int bk = t >> 4, bcn = t & 15;
    const int boff0 = bk * 16        + (bcn ^ (bk & 7));
    const int boff1 = (bk + 16) * 16 + (bcn ^ (bk & 7));

    const uint32_t asb = smem_u32(&As4[0][0]);
    const uint32_t bsb = smem_u32(&Bs4[0][0]);

    int tot = 0;
#pragma unroll
    for (int s = 0; s < 6; s++) if (s < SL.n) tot += SL.s[s].kchunks;

    float d[2][8][4];
#pragma unroll
    for (int i = 0; i < 2; i++)
#pragma unroll
        for (int j = 0; j < 8; j++)
#pragma unroll
            for (int q = 0; q < 4; q++) d[i][j][q] = 0.f;

    int ls = 0, lc = 0;   // next chunk to load: segment / chunk-in-segment

    auto issue = [&](int buf) {
        const Seg sg = SL.s[ls];
        const __nv_bfloat16* Ap = sg.A + (size_t)(m0 + am) * sg.lda + lc * 32 + ac * 8;
        CP16(asb + (uint32_t)(buf * 512 + aoff0) * 16, Ap);
        CP16(asb + (uint32_t)(buf * 512 + aoff1) * 16, Ap + (size_t)64 * sg.lda);
        const __nv_bfloat16* Bp = sg.B + (size_t)(lc * 32 + bk) * N + n0 + bcn * 8;
        CP16(bsb + (uint32_t)(buf * 512 + boff0) * 16, Bp);
        CP16(bsb + (uint32_t)(buf * 512 + boff1) * 16, Bp + (size_t)16 * N);
        asm volatile("cp.async.commit_group;\n");
        if (++lc == sg.kchunks) { lc = 0; ++ls; }
    };

    issue(0);
    int issued = 1;

    for (int i = 0; i < tot; i++) {
        const int buf = i & 1;
        if (issued < tot) { issue(issued & 1); issued++; cp_wait<1>(); }
        else              { cp_wait<0>(); }
        __syncthreads();

#pragma unroll
        for (int kk = 0; kk < 2; kk++) {
            // A fragments: 2 m16 tiles
            uint32_t a[2][4];
#pragma unroll
            for (int mi = 0; mi < 2; mi++) {
                const int mrow = wm + mi * 16 + (lane & 15);
                const int c    = kk * 2 + (lane >> 4);
                const int phys = mrow * 4 + (c ^ ((mrow >> 1) & 3));
                ldsm_x4(a[mi], asb + (uint32_t)(buf * 512 + phys) * 16);
            }
            // B fragments (4 groups of n16) + MMAs
#pragma unroll
            for (int j = 0; j < 4; j++) {
                uint32_t bb[4];
                const int krow = kk * 16 + (lane & 15);
                const int cn   = (wn >> 3) + j * 2 + (lane >> 4);
                const int phys = krow * 16 + (cn ^ (krow & 7));
                ldsm_x4_t(bb, bsb + (uint32_t)(buf * 512 + phys) * 16);
#pragma unroll
                for (int mi = 0; mi < 2; mi++) {
                    mma16816(d[mi][2 * j],     a[mi], bb[0], bb[1]);
                    mma16816(d[mi][2 * j + 1], a[mi], bb[2], bb[3]);
                }
            }
        }
        __syncthreads();
    }

    // ---- epilogue: bias + leaky-relu + hi/lo bf16 split store ----
#pragma unroll
    for (int mi = 0; mi < 2; mi++) {
#pragma unroll
        for (int j = 0; j < 8; j++) {
            const int col  = n0 + wn + j * 8 + (lane & 3) * 2;
            const float b0 = bias[col], b1 = bias[col + 1];
#pragma unroll
            for (int rh = 0; rh < 2; rh++) {
                const int row = m0 + wm + mi * 16 + (lane >> 2) + rh * 8;
                float v0 = d[mi][j][2 * rh]     + b0;
                float v1 = d[mi][j][2 * rh + 1] + b1;
                v0 = (v0 > 0.f) ? v0 : 0.02f * v0;
                v1 = (v1 > 0.f) ? v1 : 0.02f * v1;
                const size_t o = (size_t)row * N + col;
                __nv_bfloat16 h0 = __float2bfloat16(v0);
                __nv_bfloat16 h1 = __float2bfloat16(v1);
                *reinterpret_cast<__nv_bfloat162*>(out_hi + o) =
                    __nv_bfloat162(h0, h1);
                *reinterpret_cast<__nv_bfloat162*>(out_lo + o) =
                    __nv_bfloat162(__float2bfloat16(v0 - __bfloat162float(h0)),
                                   __float2bfloat16(v1 - __bfloat162float(h1)));
            }
        }
    }
}

// ---------------------------------------------------------------------------
// Final layer: out[m] = (h5hi+h5lo)[m,:] . W6 + b6   (128 -> 1)
// ---------------------------------------------------------------------------
__global__ void final_kernel(const __nv_bfloat16* __restrict__ h5hi,
                             const __nv_bfloat16* __restrict__ h5lo,
                             const float* __restrict__ W6,
                             const float* __restrict__ b6,
                             float* __restrict__ out)
{
    const int warp = threadIdx.x >> 5;
    const int lane = threadIdx.x & 31;
    const int m = blockIdx.x * 8 + warp;

    float s = 0.f;
#pragma unroll
    for (int j = 0; j < 4; j++) {
        const int c = 4 * lane + j;
        const float h = __bfloat162float(h5hi[(size_t)m * 128 + c]) +
                        __bfloat162float(h5lo[(size_t)m * 128 + c]);
        s = fmaf(h, W6[c], s);
    }
#pragma unroll
    for (int o = 16; o > 0; o >>= 1)
        s += __shfl_xor_sync(0xffffffffu, s, o);
    if (lane == 0) out[m] = s + b6[0];
}

// ---------------------------------------------------------------------------
// Launch
// ---------------------------------------------------------------------------
extern "C" void kernel_launch(void* const* d_in, const int* in_sizes, int n_in,
                              void* d_out, int out_size)
{
    (void)in_sizes; (void)n_in; (void)out_size;

    const int*   indices = (const int*)  d_in[0];
    const float* qp      = (const float*)d_in[1];
    const float* cpos    = (const float*)d_in[2];
    const float* codes   = (const float*)d_in[3];
    const float* W1 = (const float*)d_in[4];  const float* b1 = (const float*)d_in[5];
    const float* W2 = (const float*)d_in[6];  const float* b2 = (const float*)d_in[7];
    const float* W3 = (const float*)d_in[8];  const float* b3 = (const float*)d_in[9];
    const float* W4 = (const float*)d_in[10]; const float* b4 = (const float*)d_in[11];
    const float* W5 = (const float*)d_in[12]; const float* b5 = (const float*)d_in[13];
    const float* W6 = (const float*)d_in[14]; const float* b6 = (const float*)d_in[15];
    float* out = (float*)d_out;

    __nv_bfloat16 *xhi, *xlo, *h1hi, *h1lo, *h2hi, *h2lo, *h3hi, *h3lo,
                  *h4hi, *h4lo, *h5hi, *h5lo, *wsp;
    cudaGetSymbolAddress((void**)&xhi,  g_xhi);  cudaGetSymbolAddress((void**)&xlo,  g_xlo);
    cudaGetSymbolAddress((void**)&h1hi, g_h1hi); cudaGetSymbolAddress((void**)&h1lo, g_h1lo);
    cudaGetSymbolAddress((void**)&h2hi, g_h2hi); cudaGetSymbolAddress((void**)&h2lo, g_h2lo);
    cudaGetSymbolAddress((void**)&h3hi, g_h3hi); cudaGetSymbolAddress((void**)&h3lo, g_h3lo);
    cudaGetSymbolAddress((void**)&h4hi, g_h4hi); cudaGetSymbolAddress((void**)&h4lo, g_h4lo);
    cudaGetSymbolAddress((void**)&h5hi, g_h5hi); cudaGetSymbolAddress((void**)&h5lo, g_h5lo);
    cudaGetSymbolAddress((void**)&wsp,  g_wsplit);

    // split-weight plane offsets
    size_t off = 0;
    auto take = [&](size_t nelem) { size_t o = off; off += nelem; return o; };
    __nv_bfloat16* w1x_hi = wsp + take((size_t)XK * 2048);
    __nv_bfloat16* w1x_lo = wsp + take((size_t)XK * 2048);
    __nv_bfloat16* w2h_hi = wsp + take((size_t)2048 * 1024);
    __nv_bfloat16* w2h_lo = wsp + take((size_t)2048 * 1024);
    __nv_bfloat16* w2x_hi = wsp + take((size_t)XK * 1024);
    __nv_bfloat16* w2x_lo = wsp + take((size_t)XK * 1024);
    __nv_bfloat16* w3h_hi = wsp + take((size_t)1024 * 512);
    __nv_bfloat16* w3h_lo = wsp + take((size_t)1024 * 512);
    __nv_bfloat16* w3x_hi = wsp + take((size_t)XK * 512);
    __nv_bfloat16* w3x_lo = wsp + take((size_t)XK * 512);
    __nv_bfloat16* w4h_hi = wsp + take((size_t)512 * 256);
    __nv_bfloat16* w4h_lo = wsp + take((size_t)512 * 256);
    __nv_bfloat16* w4x_hi = wsp + take((size_t)XK * 256);
    __nv_bfloat16* w4x_lo = wsp + take((size_t)XK * 256);
    __nv_bfloat16* w5h_hi = wsp + take((size_t)256 * 128);
    __nv_bfloat16* w5h_lo = wsp + take((size_t)256 * 128);
    __nv_bfloat16* w5x_hi = wsp + take((size_t)XK * 128);
    __nv_bfloat16* w5x_lo = wsp + take((size_t)XK * 128);

    // weight prep
    auto prep = [&](const float* W, int K1, int N,
                    __nv_bfloat16* hh, __nv_bfloat16* hl,
                    __nv_bfloat16* xh, __nv_bfloat16* xl) {
        int tot = (K1 + XK) * N;
        prep_w<<<(tot + 255) / 256, 256>>>(W, K1, N, hh, hl, xh, xl);
    };
    prep(W1, 0,    2048, w1x_hi, w1x_lo, w1x_hi, w1x_lo);
    prep(W2, 2048, 1024, w2h_hi, w2h_lo, w2x_hi, w2x_lo);
    prep(W3, 1024, 512,  w3h_hi, w3h_lo, w3x_hi, w3x_lo);
    prep(W4, 512,  256,  w4h_hi, w4h_lo, w4x_hi, w4x_lo);
    prep(W5, 256,  128,  w5h_hi, w5h_lo, w5x_hi, w5x_lo);

    // stage 1
    const int s1_smem = NK * ND * (int)sizeof(float) + 8 * NK * (int)sizeof(float);
    cudaFuncSetAttribute(stage1_kernel, cudaFuncAttributeMaxDynamicSharedMemorySize, s1_smem);
    stage1_kernel<<<dim3(NB, NP / PPB), 256, s1_smem>>>(indices, qp, cpos, codes);

    // layers: segments implement  A_hi*B_hi + A_hi*B_lo + A_lo*B_hi  per operand pair
    auto run = [&](int N, const float* bias,
                   __nv_bfloat16* Ah, __nv_bfloat16* Al, int K1,
                   __nv_bfloat16* Whh, __nv_bfloat16* Whl,
                   __nv_bfloat16* Wxh, __nv_bfloat16* Wxl,
                   __nv_bfloat16* Ohi, __nv_bfloat16* Olo) {
        SegList SL;
        int n = 0;
        if (K1 > 0) {
            SL.s[n++] = { Ah, Whh, K1, K1 >> 5 };
            SL.s[n++] = { Ah, Whl, K1, K1 >> 5 };
            SL.s[n++] = { Al, Whh, K1, K1 >> 5 };
        }
        SL.s[n++] = { xhi, Wxh, XK, XK >> 5 };
        SL.s[n++] = { xhi, Wxl, XK, XK >> 5 };
        SL.s[n++] = { xlo, Wxh, XK, XK >> 5 };
        SL.n = n;
        mma_gemm<<<dim3(N / 128, NM / 128), 256>>>(SL, bias, N, Ohi, Olo);
    };

    run(2048, b1, nullptr, nullptr, 0,    nullptr, nullptr, w1x_hi, w1x_lo, h1hi, h1lo);
    run(1024, b2, h1hi, h1lo, 2048, w2h_hi, w2h_lo, w2x_hi, w2x_lo, h2hi, h2lo);
    run(512,  b3, h2hi, h2lo, 1024, w3h_hi, w3h_lo, w3x_hi, w3x_lo, h3hi, h3lo);
    run(256,  b4, h3hi, h3lo, 512,  w4h_hi, w4h_lo, w4x_hi, w4x_lo, h4hi, h4lo);
    run(128,  b5, h4hi, h4lo, 256,  w5h_hi, w5h_lo, w5x_hi, w5x_lo, h5hi, h5lo);

    final_kernel<<<NM / 8, 256>>>(h5hi, h5lo, W6, b6, out);
}

// round 11
// speedup vs baseline: 3.9667x; 1.3704x over previous
#include <cuda_runtime.h>
#include <cuda_fp16.h>
#include <stdint.h>

// ---------------------------------------------------------------------------
// Problem constants
// ---------------------------------------------------------------------------
#define NB   8
#define NP   8192
#define NM   (NB * NP)          // 65536 rows
#define NK   128                // codes per record
#define ND   128                // code dim
#define XK   160                // padded x K-dim (131 valid, rest zero) — mult of 32
#define PPB  128                // stage-1 points per block

// ---------------------------------------------------------------------------
// Scratch: fp16 hi/lo activation planes + fp16 weights (no allocs allowed)
// ---------------------------------------------------------------------------
__device__ __half g_xhi[(size_t)NM * XK];
__device__ __half g_xlo[(size_t)NM * XK];
__device__ __half g_h1hi[(size_t)NM * 2048];
__device__ __half g_h1lo[(size_t)NM * 2048];
__device__ __half g_h2hi[(size_t)NM * 1024];
__device__ __half g_h2lo[(size_t)NM * 1024];
__device__ __half g_h3hi[(size_t)NM * 512];
__device__ __half g_h3lo[(size_t)NM * 512];
__device__ __half g_h4hi[(size_t)NM * 256];
__device__ __half g_h4lo[(size_t)NM * 256];
__device__ __half g_h5hi[(size_t)NM * 128];
__device__ __half g_h5lo[(size_t)NM * 128];
// fp16 weights (single plane): sum of (K1+160)*N over 5 layers = 3,420,160
__device__ __half g_wq[3500000];

// ---------------------------------------------------------------------------
// Helpers
// ---------------------------------------------------------------------------
__device__ __forceinline__ void split_store(__half* hp, __half* lp, float v)
{
    __half h = __float2half(v);
    *hp = h;
    *lp = __float2half(v - __half2float(h));
}

__device__ __forceinline__ uint32_t smem_u32(const void* p)
{
    return (uint32_t)__cvta_generic_to_shared(p);
}

template<int Ngrp> __device__ __forceinline__ void cp_wait()
{
    asm volatile("cp.async.wait_group %0;\n" :: "n"(Ngrp));
}

#define CP16(dst_u32, src_ptr) \
    asm volatile("cp.async.cg.shared.global [%0], [%1], 16;\n" :: "r"(dst_u32), "l"(src_ptr))

__device__ __forceinline__ void ldsm_x4(uint32_t* r, uint32_t addr)
{
    asm volatile("ldmatrix.sync.aligned.m8n8.x4.shared.b16 {%0,%1,%2,%3}, [%4];\n"
                 : "=r"(r[0]), "=r"(r[1]), "=r"(r[2]), "=r"(r[3]) : "r"(addr));
}

__device__ __forceinline__ void ldsm_x4_t(uint32_t* r, uint32_t addr)
{
    asm volatile("ldmatrix.sync.aligned.m8n8.x4.trans.shared.b16 {%0,%1,%2,%3}, [%4];\n"
                 : "=r"(r[0]), "=r"(r[1]), "=r"(r[2]), "=r"(r[3]) : "r"(addr));
}

__device__ __forceinline__ void mma16816(float* d, const uint32_t* a, uint32_t b0, uint32_t b1)
{
    asm volatile(
        "mma.sync.aligned.m16n8k16.row.col.f32.f16.f16.f32 "
        "{%0,%1,%2,%3}, {%4,%5,%6,%7}, {%8,%9}, {%0,%1,%2,%3};\n"
        : "+f"(d[0]), "+f"(d[1]), "+f"(d[2]), "+f"(d[3])
        : "r"(a[0]), "r"(a[1]), "r"(a[2]), "r"(a[3]), "r"(b0), "r"(b1));
}

// ---------------------------------------------------------------------------
// Stage 1: inverse-square-distance weighted code interpolation -> x planes
// x[m, 0:128] = weighted codes, x[m,128:131] = query point, 131..159 = 0
// ---------------------------------------------------------------------------
__global__ void stage1_kernel(const int* __restrict__ indices,
                              const float* __restrict__ qp,
                              const float* __restrict__ codes_pos,
                              const float* __restrict__ codes)
{
    extern __shared__ float smem[];
    float4* bc4 = reinterpret_cast<float4*>(smem);   // [128 codes][32 float4]
    float*  ws  = smem + NK * ND;                    // [8 warps][128] weights

    const int b   = blockIdx.x;
    const int rec = indices[b];

    const float4* csrc = reinterpret_cast<const float4*>(codes + (size_t)rec * NK * ND);
    for (int i = threadIdx.x; i < NK * (ND / 4); i += blockDim.x)
        bc4[i] = csrc[i];
    __syncthreads();

    const int warp = threadIdx.x >> 5;
    const int lane = threadIdx.x & 31;

    const float* pbase = codes_pos + (size_t)rec * NK * 3;
    float cpx[4], cpy[4], cpz[4];
#pragma unroll
    for (int t = 0; t < 4; t++) {
        int k = lane + 32 * t;
        cpx[t] = pbase[k * 3 + 0];
        cpy[t] = pbase[k * 3 + 1];
        cpz[t] = pbase[k * 3 + 2];
    }

    float* wsw = ws + warp * NK;
    const int p0 = blockIdx.y * PPB;

    for (int pi = warp; pi < PPB; pi += 8) {
        const int m = b * NP + p0 + pi;
        const float qx = qp[(size_t)m * 3 + 0];
        const float qy = qp[(size_t)m * 3 + 1];
        const float qz = qp[(size_t)m * 3 + 2];

        float wsum = 0.f;
#pragma unroll
        for (int t = 0; t < 4; t++) {
            float dx = qx - cpx[t], dy = qy - cpy[t], dz = qz - cpz[t];
            float sq = dx * dx + dy * dy + dz * dz + 1e-16f;
            float w  = 1.0f / sq;
            wsw[lane + 32 * t] = w;
            wsum += w;
        }
        __syncwarp();
#pragma unroll
        for (int o = 16; o > 0; o >>= 1)
            wsum += __shfl_xor_sync(0xffffffffu, wsum, o);

        float4 acc = make_float4(0.f, 0.f, 0.f, 0.f);
#pragma unroll 4
        for (int k = 0; k < NK; k++) {
            const float  w = wsw[k];
            const float4 c = bc4[k * 32 + lane];
            acc.x = fmaf(w, c.x, acc.x);
            acc.y = fmaf(w, c.y, acc.y);
            acc.z = fmaf(w, c.z, acc.z);
            acc.w = fmaf(w, c.w, acc.w);
        }
        const float inv = 1.0f / wsum;

        __half* xh = g_xhi + (size_t)m * XK;
        __half* xl = g_xlo + (size_t)m * XK;
        float v[4] = { acc.x * inv, acc.y * inv, acc.z * inv, acc.w * inv };
#pragma unroll
        for (int j = 0; j < 4; j++)
            split_store(xh + 4 * lane + j, xl + 4 * lane + j, v[j]);

        // tail cols 128..159: query point then zeros (one col per lane)
        {
            const int c = 128 + lane;
            float q = 0.f;
            if (lane == 0) q = qx; else if (lane == 1) q = qy; else if (lane == 2) q = qz;
            split_store(xh + c, xl + c, q);
        }
        __syncwarp();
    }
}

// ---------------------------------------------------------------------------
// Weight prep: fp32 W[K1+131, N] -> single fp16 plane, x-part padded to 160 rows
// Layout preserved: hh[k, n] (K1 x N), xh[k2, n] (XK x N)
// ---------------------------------------------------------------------------
__global__ void prep_w(const float* __restrict__ W, int K1, int N,
                       __half* __restrict__ hh, __half* __restrict__ xh)
{
    const int idx = blockIdx.x * blockDim.x + threadIdx.x;
    const int tot = (K1 + XK) * N;
    if (idx >= tot) return;
    const int r = idx / N, n = idx - r * N;
    if (r < K1) {
        hh[(size_t)r * N + n] = __float2half(W[(size_t)r * N + n]);
    } else {
        const int r2 = r - K1;
        float v = (r2 < 131) ? W[(size_t)(K1 + r2) * N + n] : 0.f;
        xh[(size_t)r2 * N + n] = __float2half(v);
    }
}

// ---------------------------------------------------------------------------
// Segmented fp16 tensor-core GEMM with fused bias + leaky-relu + hi/lo store.
//   Out[m,n] = act( sum_seg  A_seg[m,:] @ B_seg[:,n]  + bias[n] )
// Segments implement exact-activation fp16 GEMM:
//   (Ah + Al) @ fp16(W)  — error is only fp16 weight quantization (~2^-11).
// CTA 128x128, 8 warps (32x64 each), K-chunks of 32, cp.async double buffer.
// ---------------------------------------------------------------------------
struct Seg { const __half* A; const __half* B; int lda; int kchunks; };
struct SegList { Seg s[4]; int n; };

__global__ __launch_bounds__(256, 2)
void mma_gemm(SegList SL, const float* __restrict__ bias, int N,
              __half* __restrict__ out_hi, __half* __restrict__ out_lo)
{
    __shared__ uint4 As4[2][512];   // [buf][m(128) x chunk(4)] xor-swizzled
    __shared__ uint4 Bs4[2][512];   // [buf][k(32) x chunk(16)] xor-swizzled

    const int t    = threadIdx.x;
    const int lane = t & 31;
    const int w    = t >> 5;
    const int wm   = (w & 3) * 32;   // warp M offset in tile
    const int wn   = (w >> 2) * 64;  // warp N offset in tile

    const int n0 = blockIdx.x * 128;
    const int m0 = blockIdx.y * 128;

    // loader thread-fixed coordinates
    const int am = t >> 2, ac = t & 3;
    const int aoff0 = am * 4        + (ac ^ ((am >> 1) & 3));
    const int aoff1 = (am + 64) * 4 + (ac ^ ((am >> 1) & 3));
    const int bk = t >> 4, bcn = t & 15;
    const int boff0 = bk * 16        + (bcn ^ (bk & 7));
    const int boff1 = (bk + 16) * 16 + (bcn ^ (bk & 7));

    const uint32_t asb = smem_u32(&As4[0][0]);
    const uint32_t bsb = smem_u32(&Bs4[0][0]);

    int tot = 0;
#pragma unroll
    for (int s = 0; s < 4; s++) if (s < SL.n) tot += SL.s[s].kchunks;

    float d[2][8][4];
#pragma unroll
    for (int i = 0; i < 2; i++)
#pragma unroll
        for (int j = 0; j < 8; j++)
#pragma unroll
            for (int q = 0; q < 4; q++) d[i][j][q] = 0.f;

    int ls = 0, lc = 0;   // next chunk to load: segment / chunk-in-segment

    auto issue = [&](int buf) {
        const Seg sg = SL.s[ls];
        const __half* Ap = sg.A + (size_t)(m0 + am) * sg.lda + lc * 32 + ac * 8;
        CP16(asb + (uint32_t)(buf * 512 + aoff0) * 16, Ap);
        CP16(asb + (uint32_t)(buf * 512 + aoff1) * 16, Ap + (size_t)64 * sg.lda);
        const __half* Bp = sg.B + (size_t)(lc * 32 + bk) * N + n0 + bcn * 8;
        CP16(bsb + (uint32_t)(buf * 512 + boff0) * 16, Bp);
        CP16(bsb + (uint32_t)(buf * 512 + boff1) * 16, Bp + (size_t)16 * N);
        asm volatile("cp.async.commit_group;\n");
        if (++lc == sg.kchunks) { lc = 0; ++ls; }
    };

    issue(0);
    int issued = 1;

    for (int i = 0; i < tot; i++) {
        const int buf = i & 1;
        if (issued < tot) { issue(issued & 1); issued++; cp_wait<1>(); }
        else              { cp_wait<0>(); }
        __syncthreads();

#pragma unroll
        for (int kk = 0; kk < 2; kk++) {
            // A fragments: 2 m16 tiles
            uint32_t a[2][4];
#pragma unroll
            for (int mi = 0; mi < 2; mi++) {
                const int mrow = wm + mi * 16 + (lane & 15);
                const int c    = kk * 2 + (lane >> 4);
                const int phys = mrow * 4 + (c ^ ((mrow >> 1) & 3));
                ldsm_x4(a[mi], asb + (uint32_t)(buf * 512 + phys) * 16);
            }
            // B fragments (4 groups of n16) + MMAs
#pragma unroll
            for (int j = 0; j < 4; j++) {
                uint32_t bb[4];
                const int krow = kk * 16 + (lane & 15);
                const int cn   = (wn >> 3) + j * 2 + (lane >> 4);
                const int phys = krow * 16 + (cn ^ (krow & 7));
                ldsm_x4_t(bb, bsb + (uint32_t)(buf * 512 + phys) * 16);
#pragma unroll
                for (int mi = 0; mi < 2; mi++) {
                    mma16816(d[mi][2 * j],     a[mi], bb[0], bb[1]);
                    mma16816(d[mi][2 * j + 1], a[mi], bb[2], bb[3]);
                }
            }
        }
        __syncthreads();
    }

    // ---- epilogue: bias + leaky-relu + hi/lo fp16 split store ----
#pragma unroll
    for (int mi = 0; mi < 2; mi++) {
#pragma unroll
        for (int j = 0; j < 8; j++) {
            const int col  = n0 + wn + j * 8 + (lane & 3) * 2;
            const float b0 = bias[col], b1 = bias[col + 1];
#pragma unroll
            for (int rh = 0; rh < 2; rh++) {
                const int row = m0 + wm + mi * 16 + (lane >> 2) + rh * 8;
                float v0 = d[mi][j][2 * rh]     + b0;
                float v1 = d[mi][j][2 * rh + 1] + b1;
                v0 = (v0 > 0.f) ? v0 : 0.02f * v0;
                v1 = (v1 > 0.f) ? v1 : 0.02f * v1;
                const size_t o = (size_t)row * N + col;
                __half h0 = __float2half(v0);
                __half h1 = __float2half(v1);
                *reinterpret_cast<__half2*>(out_hi + o) = __halves2half2(h0, h1);
                *reinterpret_cast<__half2*>(out_lo + o) =
                    __halves2half2(__float2half(v0 - __half2float(h0)),
                                   __float2half(v1 - __half2float(h1)));
            }
        }
    }
}

// ---------------------------------------------------------------------------
// Final layer: out[m] = (h5hi+h5lo)[m,:] . W6 + b6   (128 -> 1)
// ---------------------------------------------------------------------------
__global__ void final_kernel(const __half* __restrict__ h5hi,
                             const __half* __restrict__ h5lo,
                             const float* __restrict__ W6,
                             const float* __restrict__ b6,
                             float* __restrict__ out)
{
    const int warp = threadIdx.x >> 5;
    const int lane = threadIdx.x & 31;
    const int m = blockIdx.x * 8 + warp;

    float s = 0.f;
#pragma unroll
    for (int j = 0; j < 4; j++) {
        const int c = 4 * lane + j;
        const float h = __half2float(h5hi[(size_t)m * 128 + c]) +
                        __half2float(h5lo[(size_t)m * 128 + c]);
        s = fmaf(h, W6[c], s);
    }
#pragma unroll
    for (int o = 16; o > 0; o >>= 1)
        s += __shfl_xor_sync(0xffffffffu, s, o);
    if (lane == 0) out[m] = s + b6[0];
}

// ---------------------------------------------------------------------------
// Launch
// ---------------------------------------------------------------------------
extern "C" void kernel_launch(void* const* d_in, const int* in_sizes, int n_in,
                              void* d_out, int out_size)
{
    (void)in_sizes; (void)n_in; (void)out_size;

    const int*   indices = (const int*)  d_in[0];
    const float* qp      = (const float*)d_in[1];
    const float* cpos    = (const float*)d_in[2];
    const float* codes   = (const float*)d_in[3];
    const float* W1 = (const float*)d_in[4];  const float* b1 = (const float*)d_in[5];
    const float* W2 = (const float*)d_in[6];  const float* b2 = (const float*)d_in[7];
    const float* W3 = (const float*)d_in[8];  const float* b3 = (const float*)d_in[9];
    const float* W4 = (const float*)d_in[10]; const float* b4 = (const float*)d_in[11];
    const float* W5 = (const float*)d_in[12]; const float* b5 = (const float*)d_in[13];
    const float* W6 = (const float*)d_in[14]; const float* b6 = (const float*)d_in[15];
    float* out = (float*)d_out;

    __half *xhi, *xlo, *h1hi, *h1lo, *h2hi, *h2lo, *h3hi, *h3lo,
           *h4hi, *h4lo, *h5hi, *h5lo, *wq;
    cudaGetSymbolAddress((void**)&xhi,  g_xhi);  cudaGetSymbolAddress((void**)&xlo,  g_xlo);
    cudaGetSymbolAddress((void**)&h1hi, g_h1hi); cudaGetSymbolAddress((void**)&h1lo, g_h1lo);
    cudaGetSymbolAddress((void**)&h2hi, g_h2hi); cudaGetSymbolAddress((void**)&h2lo, g_h2lo);
    cudaGetSymbolAddress((void**)&h3hi, g_h3hi); cudaGetSymbolAddress((void**)&h3lo, g_h3lo);
    cudaGetSymbolAddress((void**)&h4hi, g_h4hi); cudaGetSymbolAddress((void**)&h4lo, g_h4lo);
    cudaGetSymbolAddress((void**)&h5hi, g_h5hi); cudaGetSymbolAddress((void**)&h5lo, g_h5lo);
    cudaGetSymbolAddress((void**)&wq,   g_wq);

    // weight plane offsets (single fp16 plane per part)
    size_t off = 0;
    auto take = [&](size_t nelem) { __half* p = wq + off; off += nelem; return p; };
    __half* w1x = take((size_t)XK * 2048);
    __half* w2h = take((size_t)2048 * 1024);
    __half* w2x = take((size_t)XK * 1024);
    __half* w3h = take((size_t)1024 * 512);
    __half* w3x = take((size_t)XK * 512);
    __half* w4h = take((size_t)512 * 256);
    __half* w4x = take((size_t)XK * 256);
    __half* w5h = take((size_t)256 * 128);
    __half* w5x = take((size_t)XK * 128);

    // weight prep (fp32 -> fp16, x-part padded to 160 rows)
    auto prep = [&](const float* W, int K1, int N, __half* hh, __half* xh) {
        int tot = (K1 + XK) * N;
        prep_w<<<(tot + 255) / 256, 256>>>(W, K1, N, hh, xh);
    };
    prep(W1, 0,    2048, w1x, w1x);
    prep(W2, 2048, 1024, w2h, w2x);
    prep(W3, 1024, 512,  w3h, w3x);
    prep(W4, 512,  256,  w4h, w4x);
    prep(W5, 256,  128,  w5h, w5x);

    // stage 1
    const int s1_smem = NK * ND * (int)sizeof(float) + 8 * NK * (int)sizeof(float);
    cudaFuncSetAttribute(stage1_kernel, cudaFuncAttributeMaxDynamicSharedMemorySize, s1_smem);
    stage1_kernel<<<dim3(NB, NP / PPB), 256, s1_smem>>>(indices, qp, cpos, codes);

    // layers: segments implement  (Ah + Al) @ W  exactly (fp16 planes)
    auto run = [&](int N, const float* bias,
                   __half* Ah, __half* Al, int K1, __half* Wh, __half* Wx,
                   __half* Ohi, __half* Olo) {
        SegList SL;
        int n = 0;
        if (K1 > 0) {
            SL.s[n++] = { Ah, Wh, K1, K1 >> 5 };
            SL.s[n++] = { Al, Wh, K1, K1 >> 5 };
        }
        SL.s[n++] = { xhi, Wx, XK, XK >> 5 };
        SL.s[n++] = { xlo, Wx, XK, XK >> 5 };
        SL.n = n;
        mma_gemm<<<dim3(N / 128, NM / 128), 256>>>(SL, bias, N, Ohi, Olo);
    };

    run(2048, b1, nullptr, nullptr, 0,    nullptr, w1x, h1hi, h1lo);
    run(1024, b2, h1hi, h1lo, 2048, w2h, w2x, h2hi, h2lo);
    run(512,  b3, h2hi, h2lo, 1024, w3h, w3x, h3hi, h3lo);
    run(256,  b4, h3hi, h3lo, 512,  w4h, w4x, h4hi, h4lo);
    run(128,  b5, h4hi, h4lo, 256,  w5h, w5x, h5hi, h5lo);

    // Final 128 -> 1 dot
    final_kernel<<<NM / 8, 256>>>(h5hi, h5lo, W6, b6, out);
}

// round 12
// speedup vs baseline: 6.4133x; 1.6168x over previous
#include <cuda_runtime.h>
#include <cuda_fp16.h>
#include <stdint.h>

// ---------------------------------------------------------------------------
// Problem constants
// ---------------------------------------------------------------------------
#define NB   8
#define NP   8192
#define NM   (NB * NP)          // 65536 rows
#define NK   128                // codes per record
#define ND   128                // code dim
#define XK   160                // padded x K-dim (131 valid, rest zero) — mult of 32
#define PPB  128                // stage-1 points per block

// ---------------------------------------------------------------------------
// Scratch: x keeps hi/lo fp16 planes; h activations are single fp16 planes.
// ---------------------------------------------------------------------------
__device__ __half g_xhi[(size_t)NM * XK];
__device__ __half g_xlo[(size_t)NM * XK];
__device__ __half g_h1[(size_t)NM * 2048];
__device__ __half g_h2[(size_t)NM * 1024];
__device__ __half g_h3[(size_t)NM * 512];
__device__ __half g_h4[(size_t)NM * 256];
__device__ __half g_h5[(size_t)NM * 128];
// fp16 weights (single plane): sum of (K1+160)*N over 5 layers = 3,420,160
__device__ __half g_wq[3500000];

// ---------------------------------------------------------------------------
// Helpers
// ---------------------------------------------------------------------------
__device__ __forceinline__ void split_store(__half* hp, __half* lp, float v)
{
    __half h = __float2half(v);
    *hp = h;
    *lp = __float2half(v - __half2float(h));
}

__device__ __forceinline__ uint32_t smem_u32(const void* p)
{
    return (uint32_t)__cvta_generic_to_shared(p);
}

template<int Ngrp> __device__ __forceinline__ void cp_wait()
{
    asm volatile("cp.async.wait_group %0;\n" :: "n"(Ngrp));
}

#define CP16(dst_u32, src_ptr) \
    asm volatile("cp.async.cg.shared.global [%0], [%1], 16;\n" :: "r"(dst_u32), "l"(src_ptr))

__device__ __forceinline__ void ldsm_x4(uint32_t* r, uint32_t addr)
{
    asm volatile("ldmatrix.sync.aligned.m8n8.x4.shared.b16 {%0,%1,%2,%3}, [%4];\n"
                 : "=r"(r[0]), "=r"(r[1]), "=r"(r[2]), "=r"(r[3]) : "r"(addr));
}

__device__ __forceinline__ void ldsm_x4_t(uint32_t* r, uint32_t addr)
{
    asm volatile("ldmatrix.sync.aligned.m8n8.x4.trans.shared.b16 {%0,%1,%2,%3}, [%4];\n"
                 : "=r"(r[0]), "=r"(r[1]), "=r"(r[2]), "=r"(r[3]) : "r"(addr));
}

__device__ __forceinline__ void mma16816(float* d, const uint32_t* a, uint32_t b0, uint32_t b1)
{
    asm volatile(
        "mma.sync.aligned.m16n8k16.row.col.f32.f16.f16.f32 "
        "{%0,%1,%2,%3}, {%4,%5,%6,%7}, {%8,%9}, {%0,%1,%2,%3};\n"
        : "+f"(d[0]), "+f"(d[1]), "+f"(d[2]), "+f"(d[3])
        : "r"(a[0]), "r"(a[1]), "r"(a[2]), "r"(a[3]), "r"(b0), "r"(b1));
}

// ---------------------------------------------------------------------------
// Stage 1: inverse-square-distance weighted code interpolation -> x planes
// x[m, 0:128] = weighted codes, x[m,128:131] = query point, 131..159 = 0
// ---------------------------------------------------------------------------
__global__ void stage1_kernel(const int* __restrict__ indices,
                              const float* __restrict__ qp,
                              const float* __restrict__ codes_pos,
                              const float* __restrict__ codes)
{
    extern __shared__ float smem[];
    float4* bc4 = reinterpret_cast<float4*>(smem);   // [128 codes][32 float4]
    float*  ws  = smem + NK * ND;                    // [8 warps][128] weights

    const int b   = blockIdx.x;
    const int rec = indices[b];

    const float4* csrc = reinterpret_cast<const float4*>(codes + (size_t)rec * NK * ND);
    for (int i = threadIdx.x; i < NK * (ND / 4); i += blockDim.x)
        bc4[i] = csrc[i];
    __syncthreads();

    const int warp = threadIdx.x >> 5;
    const int lane = threadIdx.x & 31;

    const float* pbase = codes_pos + (size_t)rec * NK * 3;
    float cpx[4], cpy[4], cpz[4];
#pragma unroll
    for (int t = 0; t < 4; t++) {
        int k = lane + 32 * t;
        cpx[t] = pbase[k * 3 + 0];
        cpy[t] = pbase[k * 3 + 1];
        cpz[t] = pbase[k * 3 + 2];
    }

    float* wsw = ws + warp * NK;
    const int p0 = blockIdx.y * PPB;

    for (int pi = warp; pi < PPB; pi += 8) {
        const int m = b * NP + p0 + pi;
        const float qx = qp[(size_t)m * 3 + 0];
        const float qy = qp[(size_t)m * 3 + 1];
        const float qz = qp[(size_t)m * 3 + 2];

        float wsum = 0.f;
#pragma unroll
        for (int t = 0; t < 4; t++) {
            float dx = qx - cpx[t], dy = qy - cpy[t], dz = qz - cpz[t];
            float sq = dx * dx + dy * dy + dz * dz + 1e-16f;
            float w  = 1.0f / sq;
            wsw[lane + 32 * t] = w;
            wsum += w;
        }
        __syncwarp();
#pragma unroll
        for (int o = 16; o > 0; o >>= 1)
            wsum += __shfl_xor_sync(0xffffffffu, wsum, o);

        float4 acc = make_float4(0.f, 0.f, 0.f, 0.f);
#pragma unroll 4
        for (int k = 0; k < NK; k++) {
            const float  w = wsw[k];
            const float4 c = bc4[k * 32 + lane];
            acc.x = fmaf(w, c.x, acc.x);
            acc.y = fmaf(w, c.y, acc.y);
            acc.z = fmaf(w, c.z, acc.z);
            acc.w = fmaf(w, c.w, acc.w);
        }
        const float inv = 1.0f / wsum;

        __half* xh = g_xhi + (size_t)m * XK;
        __half* xl = g_xlo + (size_t)m * XK;
        float v[4] = { acc.x * inv, acc.y * inv, acc.z * inv, acc.w * inv };
#pragma unroll
        for (int j = 0; j < 4; j++)
            split_store(xh + 4 * lane + j, xl + 4 * lane + j, v[j]);

        // tail cols 128..159: query point then zeros (one col per lane)
        {
            const int c = 128 + lane;
            float q = 0.f;
            if (lane == 0) q = qx; else if (lane == 1) q = qy; else if (lane == 2) q = qz;
            split_store(xh + c, xl + c, q);
        }
        __syncwarp();
    }
}

// ---------------------------------------------------------------------------
// Weight prep: fp32 W[K1+131, N] -> single fp16 plane, x-part padded to 160 rows
// Layout preserved: hh[k, n] (K1 x N), xh[k2, n] (XK x N)
// ---------------------------------------------------------------------------
__global__ void prep_w(const float* __restrict__ W, int K1, int N,
                       __half* __restrict__ hh, __half* __restrict__ xh)
{
    const int idx = blockIdx.x * blockDim.x + threadIdx.x;
    const int tot = (K1 + XK) * N;
    if (idx >= tot) return;
    const int r = idx / N, n = idx - r * N;
    if (r < K1) {
        hh[(size_t)r * N + n] = __float2half(W[(size_t)r * N + n]);
    } else {
        const int r2 = r - K1;
        float v = (r2 < 131) ? W[(size_t)(K1 + r2) * N + n] : 0.f;
        xh[(size_t)r2 * N + n] = __float2half(v);
    }
}

// ---------------------------------------------------------------------------
// Segmented fp16 tensor-core GEMM with fused bias + leaky-relu + fp16 store.
//   Out[m,n] = act( sum_seg  A_seg[m,:] @ B_seg[:,n]  + bias[n] )
// Segments: h (single fp16 plane) + x (exact hi+lo fp16 pair) vs fp16 weights.
// CTA 128x128, 8 warps (32x64 each), K-chunks of 32, cp.async double buffer.
// ---------------------------------------------------------------------------
struct Seg { const __half* A; const __half* B; int lda; int kchunks; };
struct SegList { Seg s[4]; int n; };

__global__ __launch_bounds__(256, 2)
void mma_gemm(SegList SL, const float* __restrict__ bias, int N,
              __half* __restrict__ out_hi, __half* __restrict__ out_lo,
              int store_lo)
{
    __shared__ uint4 As4[2][512];   // [buf][m(128) x chunk(4)] xor-swizzled
    __shared__ uint4 Bs4[2][512];   // [buf][k(32) x chunk(16)] xor-swizzled

    const int t    = threadIdx.x;
    const int lane = t & 31;
    const int w    = t >> 5;
    const int wm   = (w & 3) * 32;   // warp M offset in tile
    const int wn   = (w >> 2) * 64;  // warp N offset in tile

    const int n0 = blockIdx.x * 128;
    const int m0 = blockIdx.y * 128;

    // loader thread-fixed coordinates
    const int am = t >> 2, ac = t & 3;
    const int aoff0 = am * 4        + (ac ^ ((am >> 1) & 3));
    const int aoff1 = (am + 64) * 4 + (ac ^ ((am >> 1) & 3));
    const int bk = t >> 4, bcn = t & 15;
    const int boff0 = bk * 16        + (bcn ^ (bk & 7));
    const int boff1 = (bk + 16) * 16 + (bcn ^ (bk & 7));

    const uint32_t asb = smem_u32(&As4[0][0]);
    const uint32_t bsb = smem_u32(&Bs4[0][0]);

    int tot = 0;
#pragma unroll
    for (int s = 0; s < 4; s++) if (s < SL.n) tot += SL.s[s].kchunks;

    float d[2][8][4];
#pragma unroll
    for (int i = 0; i < 2; i++)
#pragma unroll
        for (int j = 0; j < 8; j++)
#pragma unroll
            for (int q = 0; q < 4; q++) d[i][j][q] = 0.f;

    int ls = 0, lc = 0;   // next chunk to load: segment / chunk-in-segment

    auto issue = [&](int buf) {
        const Seg sg = SL.s[ls];
        const __half* Ap = sg.A + (size_t)(m0 + am) * sg.lda + lc * 32 + ac * 8;
        CP16(asb + (uint32_t)(buf * 512 + aoff0) * 16, Ap);
        CP16(asb + (uint32_t)(buf * 512 + aoff1) * 16, Ap + (size_t)64 * sg.lda);
        const __half* Bp = sg.B + (size_t)(lc * 32 + bk) * N + n0 + bcn * 8;
        CP16(bsb + (uint32_t)(buf * 512 + boff0) * 16, Bp);
        CP16(bsb + (uint32_t)(buf * 512 + boff1) * 16, Bp + (size_t)16 * N);
        asm volatile("cp.async.commit_group;\n");
        if (++lc == sg.kchunks) { lc = 0; ++ls; }
    };

    issue(0);
    int issued = 1;

    for (int i = 0; i < tot; i++) {
        const int buf = i & 1;
        if (issued < tot) { issue(issued & 1); issued++; cp_wait<1>(); }
        else              { cp_wait<0>(); }
        __syncthreads();

#pragma unroll
        for (int kk = 0; kk < 2; kk++) {
            // A fragments: 2 m16 tiles
            uint32_t a[2][4];
#pragma unroll
            for (int mi = 0; mi < 2; mi++) {
                const int mrow = wm + mi * 16 + (lane & 15);
                const int c    = kk * 2 + (lane >> 4);
                const int phys = mrow * 4 + (c ^ ((mrow >> 1) & 3));
                ldsm_x4(a[mi], asb + (uint32_t)(buf * 512 + phys) * 16);
            }
            // B fragments (4 groups of n16) + MMAs
#pragma unroll
            for (int j = 0; j < 4; j++) {
                uint32_t bb[4];
                const int krow = kk * 16 + (lane & 15);
                const int cn   = (wn >> 3) + j * 2 + (lane >> 4);
                const int phys = krow * 16 + (cn ^ (krow & 7));
                ldsm_x4_t(bb, bsb + (uint32_t)(buf * 512 + phys) * 16);
#pragma unroll
                for (int mi = 0; mi < 2; mi++) {
                    mma16816(d[mi][2 * j],     a[mi], bb[0], bb[1]);
                    mma16816(d[mi][2 * j + 1], a[mi], bb[2], bb[3]);
                }
            }
        }
        __syncthreads();
    }

    // ---- epilogue: bias + leaky-relu + fp16 store (lo plane optional) ----
#pragma unroll
    for (int mi = 0; mi < 2; mi++) {
#pragma unroll
        for (int j = 0; j < 8; j++) {
            const int col  = n0 + wn + j * 8 + (lane & 3) * 2;
            const float b0 = bias[col], b1 = bias[col + 1];
#pragma unroll
            for (int rh = 0; rh < 2; rh++) {
                const int row = m0 + wm + mi * 16 + (lane >> 2) + rh * 8;
                float v0 = d[mi][j][2 * rh]     + b0;
                float v1 = d[mi][j][2 * rh + 1] + b1;
                v0 = (v0 > 0.f) ? v0 : 0.02f * v0;
                v1 = (v1 > 0.f) ? v1 : 0.02f * v1;
                const size_t o = (size_t)row * N + col;
                __half h0 = __float2half(v0);
                __half h1 = __float2half(v1);
                *reinterpret_cast<__half2*>(out_hi + o) = __halves2half2(h0, h1);
                if (store_lo) {
                    *reinterpret_cast<__half2*>(out_lo + o) =
                        __halves2half2(__float2half(v0 - __half2float(h0)),
                                       __float2half(v1 - __half2float(h1)));
                }
            }
        }
    }
}

// ---------------------------------------------------------------------------
// Final layer: out[m] = h5[m,:] . W6 + b6   (128 -> 1)
// ---------------------------------------------------------------------------
__global__ void final_kernel(const __half* __restrict__ h5,
                             const float* __restrict__ W6,
                             const float* __restrict__ b6,
                             float* __restrict__ out)
{
    const int warp = threadIdx.x >> 5;
    const int lane = threadIdx.x & 31;
    const int m = blockIdx.x * 8 + warp;

    float s = 0.f;
#pragma unroll
    for (int j = 0; j < 4; j++) {
        const int c = 4 * lane + j;
        s = fmaf(__half2float(h5[(size_t)m * 128 + c]), W6[c], s);
    }
#pragma unroll
    for (int o = 16; o > 0; o >>= 1)
        s += __shfl_xor_sync(0xffffffffu, s, o);
    if (lane == 0) out[m] = s + b6[0];
}

// ---------------------------------------------------------------------------
// Launch
// ---------------------------------------------------------------------------
extern "C" void kernel_launch(void* const* d_in, const int* in_sizes, int n_in,
                              void* d_out, int out_size)
{
    (void)in_sizes; (void)n_in; (void)out_size;

    const int*   indices = (const int*)  d_in[0];
    const float* qp      = (const float*)d_in[1];
    const float* cpos    = (const float*)d_in[2];
    const float* codes   = (const float*)d_in[3];
    const float* W1 = (const float*)d_in[4];  const float* b1 = (const float*)d_in[5];
    const float* W2 = (const float*)d_in[6];  const float* b2 = (const float*)d_in[7];
    const float* W3 = (const float*)d_in[8];  const float* b3 = (const float*)d_in[9];
    const float* W4 = (const float*)d_in[10]; const float* b4 = (const float*)d_in[11];
    const float* W5 = (const float*)d_in[12]; const float* b5 = (const float*)d_in[13];
    const float* W6 = (const float*)d_in[14]; const float* b6 = (const float*)d_in[15];
    float* out = (float*)d_out;

    __half *xhi, *xlo, *h1, *h2, *h3, *h4, *h5, *wq;
    cudaGetSymbolAddress((void**)&xhi, g_xhi); cudaGetSymbolAddress((void**)&xlo, g_xlo);
    cudaGetSymbolAddress((void**)&h1,  g_h1);  cudaGetSymbolAddress((void**)&h2,  g_h2);
    cudaGetSymbolAddress((void**)&h3,  g_h3);  cudaGetSymbolAddress((void**)&h4,  g_h4);
    cudaGetSymbolAddress((void**)&h5,  g_h5);  cudaGetSymbolAddress((void**)&wq,  g_wq);

    // weight plane offsets (single fp16 plane per part)
    size_t off = 0;
    auto take = [&](size_t nelem) { __half* p = wq + off; off += nelem; return p; };
    __half* w1x = take((size_t)XK * 2048);
    __half* w2h = take((size_t)2048 * 1024);
    __half* w2x = take((size_t)XK * 1024);
    __half* w3h = take((size_t)1024 * 512);
    __half* w3x = take((size_t)XK * 512);
    __half* w4h = take((size_t)512 * 256);
    __half* w4x = take((size_t)XK * 256);
    __half* w5h = take((size_t)256 * 128);
    __half* w5x = take((size_t)XK * 128);

    // weight prep (fp32 -> fp16, x-part padded to 160 rows)
    auto prep = [&](const float* W, int K1, int N, __half* hh, __half* xh) {
        int tot = (K1 + XK) * N;
        prep_w<<<(tot + 255) / 256, 256>>>(W, K1, N, hh, xh);
    };
    prep(W1, 0,    2048, w1x, w1x);
    prep(W2, 2048, 1024, w2h, w2x);
    prep(W3, 1024, 512,  w3h, w3x);
    prep(W4, 512,  256,  w4h, w4x);
    prep(W5, 256,  128,  w5h, w5x);

    // stage 1
    const int s1_smem = NK * ND * (int)sizeof(float) + 8 * NK * (int)sizeof(float);
    cudaFuncSetAttribute(stage1_kernel, cudaFuncAttributeMaxDynamicSharedMemorySize, s1_smem);
    stage1_kernel<<<dim3(NB, NP / PPB), 256, s1_smem>>>(indices, qp, cpos, codes);

    // layers:  act( h @ Wh  +  (xhi + xlo) @ Wx  + b ) ; h stored single fp16
    auto run = [&](int N, const float* bias,
                   __half* Ah, int K1, __half* Wh, __half* Wx, __half* Oh) {
        SegList SL;
        int n = 0;
        if (K1 > 0) SL.s[n++] = { Ah, Wh, K1, K1 >> 5 };
        SL.s[n++] = { xhi, Wx, XK, XK >> 5 };
        SL.s[n++] = { xlo, Wx, XK, XK >> 5 };
        SL.n = n;
        mma_gemm<<<dim3(N / 128, NM / 128), 256>>>(SL, bias, N, Oh, Oh, 0);
    };

    run(2048, b1, nullptr, 0,    nullptr, w1x, h1);
    run(1024, b2, h1, 2048, w2h, w2x, h2);
    run(512,  b3, h2, 1024, w3h, w3x, h3);
    run(256,  b4, h3, 512,  w4h, w4x, h4);
    run(128,  b5, h4, 256,  w5h, w5x, h5);

    // Final 128 -> 1 dot
    final_kernel<<<NM / 8, 256>>>(h5, W6, b6, out);
}